// round 11
// baseline (speedup 1.0000x reference)
#include <cuda_runtime.h>

#define MARGIN 0.1f
constexpr int Bn = 8192;
constexpr int Ln = 1024;
constexpr int WPB = 2;                 // 2 independent warps per block, 1 row each
constexpr int BLOCKS = Bn / WPB;       // 4096

// Deterministic Q32.32 fixed-point accumulators (integer atomics = associative).
// Last warp drains via atomicExch -> zeroed for the next graph replay.
__device__ unsigned long long g_acc_bce, g_acc_hinge, g_acc_valid, g_acc_sim;
__device__ unsigned int       g_done;

__global__ void __launch_bounds__(WPB * 32)
fused_kernel(const float4* __restrict__ scores4,
             const int*    __restrict__ lens,
             const float4* __restrict__ labels4,
             const float*  __restrict__ sim,
             float*        __restrict__ out)
{
    const int lane = threadIdx.x & 31;
    const int row  = blockIdx.x * WPB + (threadIdx.x >> 5);
    const unsigned FULL = 0xffffffffu;

    const int len = lens[row];
    const int ng  = (len + 127) >> 7;            // valid 128-elem groups (>=1)
    const float4* __restrict__ srow = scores4 + row * (Ln / 4);
    const float4* __restrict__ lrow = labels4 + row * (Ln / 4);
    const float simv = (lane == 0) ? sim[row] : 0.f;   // early, hidden by pass 1

    // ---- pass 1 (pipelined): BCE(log2), pos count/score, pos bitmask ----
    float lg = 0.f, pcnt = 0.f, psum = 0.f;
    unsigned pmask = 0u;                          // bit (4j+k): valid positive

    float4 sc = srow[lane];
    float4 lc = lrow[lane];
    for (int j = 0; j < ng; ++j) {
        float4 sn = sc, ln_ = lc;
        if (j + 1 < ng) {                         // prefetch next group
            sn  = srow[lane + 32 * (j + 1)];
            ln_ = lrow[lane + 32 * (j + 1)];
        }
        const float sv[4] = {sc.x, sc.y, sc.z, sc.w};
        const float lv[4] = {lc.x, lc.y, lc.z, lc.w};
        if (128 * (j + 1) <= len) {               // warp-uniform: fully valid
#pragma unroll
            for (int k = 0; k < 4; ++k) {
                const float s = sv[k], l = lv[k];
                const float sel = fmaf(l, fmaf(2.f, s, -1.f), 1.f - s); // l?s:1-s
                lg   += __log2f(sel);
                pcnt += l;
                psum  = fmaf(l, s, psum);
                pmask |= (unsigned)(l == 1.0f) << (4 * j + k);
            }
        } else {                                  // single boundary group
            const int e0 = 4 * (lane + 32 * j);
#pragma unroll
            for (int k = 0; k < 4; ++k) {
                if (e0 + k < len) {
                    const float s = sv[k], l = lv[k];
                    const float sel = fmaf(l, fmaf(2.f, s, -1.f), 1.f - s);
                    lg   += __log2f(sel);
                    pcnt += l;
                    psum  = fmaf(l, s, psum);
                    pmask |= (unsigned)(l == 1.0f) << (4 * j + k);
                }
            }
        }
        sc = sn; lc = ln_;
    }
    // -100 clamp of reference is inert: scores in (1e-4,1-1e-4) => |log| <= 9.3
    const float bce = -0.693147180559945f * lg;

    // butterfly so every lane holds chosen (bit-deterministic)
    float pc_t = pcnt, ps_t = psum;
#pragma unroll
    for (int o = 16; o; o >>= 1) {
        pc_t += __shfl_xor_sync(FULL, pc_t, o);
        ps_t += __shfl_xor_sync(FULL, ps_t, o);
    }
    const float chosen = (pc_t > 0.f) ? ps_t : -MARGIN;
    const float cm = MARGIN - chosen;

    // ---- pass 2 (scores only, L1-hot): hinge over valid negatives ----
    float hinge = 0.f;
    float4 sc2 = srow[lane];
    for (int j = 0; j < ng; ++j) {
        float4 sn2 = sc2;
        if (j + 1 < ng) sn2 = srow[lane + 32 * (j + 1)];
        const float sv[4] = {sc2.x, sc2.y, sc2.z, sc2.w};
        if (128 * (j + 1) <= len) {
#pragma unroll
            for (int k = 0; k < 4; ++k) {
                const float h = fmaxf(sv[k] + cm, 0.f);
                hinge += ((pmask >> (4 * j + k)) & 1u) ? 0.f : h;
            }
        } else {
            const int e0 = 4 * (lane + 32 * j);
#pragma unroll
            for (int k = 0; k < 4; ++k) {
                if (e0 + k < len && !((pmask >> (4 * j + k)) & 1u))
                    hinge += fmaxf(sv[k] + cm, 0.f);
            }
        }
        sc2 = sn2;
    }

    // fused reduce of (bce, hinge) to lane 0
    float bce_r = bce, h_r = hinge;
#pragma unroll
    for (int o = 16; o; o >>= 1) {
        bce_r += __shfl_down_sync(FULL, bce_r, o);
        h_r   += __shfl_down_sync(FULL, h_r,   o);
    }

    // ---- per-warp (per-row) deterministic accumulation; no barriers at all ----
    if (lane == 0) {
        const float flen = (float)len;
        const float negc = flen - pc_t;
        const bool  val  = (len > 0) && (negc > 0.f);
        const float bce_per = bce_r / ((float)Ln * flen);  // (bce*mask).mean(1)/mask.sum(1)
        const float hrow    = val ? h_r / fmaxf(negc, 1.0f) : 0.f;

        const double SC = 4294967296.0;
        atomicAdd(&g_acc_bce,   (unsigned long long)__double2ll_rn((double)bce_per * SC));
        atomicAdd(&g_acc_hinge, (unsigned long long)__double2ll_rn((double)hrow    * SC));
        if (val) atomicAdd(&g_acc_valid, 1ULL);
        atomicAdd(&g_acc_sim,   (unsigned long long)__double2ll_rn((double)simv    * SC));

        __threadfence();
        const unsigned ticket = atomicAdd(&g_done, 1u);
        if (ticket == (unsigned)(Bn - 1)) {
            const long long ib = (long long)atomicExch(&g_acc_bce,   0ULL);
            const long long ih = (long long)atomicExch(&g_acc_hinge, 0ULL);
            const long long iv = (long long)atomicExch(&g_acc_valid, 0ULL);
            const long long is = (long long)atomicExch(&g_acc_sim,   0ULL);
            atomicExch(&g_done, 0u);

            const double INV = 1.0 / 4294967296.0;
            const double Bsum = (double)ib * INV;
            const double Hsum = (double)ih * INV;
            const double Vcnt = (double)iv;
            const double Ssum = (double)is * INV;

            const double bce_loss   = Bsum / (double)Bn;
            const double hinge_loss = (Vcnt > 0.0) ? Hsum / ((Vcnt > 1.0) ? Vcnt : 1.0) : 0.0;
            const double sim_loss   = -Ssum / (double)Bn;
            const double combined   = hinge_loss + bce_loss + sim_loss;
            out[0] = (float)combined;
            out[1] = (float)hinge_loss;
            out[2] = (float)bce_loss;
            out[3] = (float)sim_loss;
        }
    }
}

extern "C" void kernel_launch(void* const* d_in, const int* in_sizes, int n_in,
                              void* d_out, int out_size)
{
    const float4* scores4 = (const float4*)d_in[0];
    const int*    lens    = (const int*)d_in[1];
    const float4* labels4 = (const float4*)d_in[2];
    const float*  sim     = (const float*)d_in[3];
    float* out = (float*)d_out;

    fused_kernel<<<BLOCKS, WPB * 32>>>(scores4, lens, labels4, sim, out);
}

// round 12
// speedup vs baseline: 1.0435x; 1.0435x over previous
#include <cuda_runtime.h>

#define MARGIN 0.1f
constexpr int Bn = 8192;
constexpr int Ln = 1024;
constexpr int FBLK = 16;               // final-kernel blocks (16*512 = 8192 rows)

// Per-row scratch (no atomics in the hot kernel -> fast CTA retirement)
__device__ float g_row_bce[Bn];
__device__ float g_row_hinge[Bn];
__device__ float g_row_valid[Bn];

// Deterministic Q32.32 combine state for the final kernel
__device__ unsigned long long g_acc_bce, g_acc_hinge, g_acc_valid, g_acc_sim;
__device__ unsigned int       g_done;

__global__ void __launch_bounds__(256)
row_kernel(const float4* __restrict__ scores4,
           const int*    __restrict__ lens,
           const float4* __restrict__ labels4)
{
    const int row = blockIdx.x;
    const int tid = threadIdx.x;
    const int len = lens[row];
    const int e0  = 4 * tid;
    const unsigned FULL = 0xffffffffu;

    // Predicated loads: warps fully beyond len skip their cache lines entirely
    // (traffic 64MB -> ~37.5MB for uniform lens), while load issue stays
    // front-batched and uniform (R1's 3.8 TB/s block-per-row behavior).
    float4 s4 = make_float4(0.f, 0.f, 0.f, 0.f);
    float4 l4 = make_float4(0.f, 0.f, 0.f, 0.f);
    if (e0 < len) {
        s4 = scores4[row * 256 + tid];
        l4 = labels4[row * 256 + tid];
    }
    const float sv[4] = {s4.x, s4.y, s4.z, s4.w};
    const float lv[4] = {l4.x, l4.y, l4.z, l4.w};

    // ---- pass 1: BCE(log2) + positive count / positive-score sum ----
    float lg = 0.f, pcnt = 0.f, psum = 0.f;
    if (e0 + 4 <= len) {                  // fully valid (common case)
#pragma unroll
        for (int k = 0; k < 4; ++k) {
            const float s = sv[k], l = lv[k];
            const float sel = fmaf(l, fmaf(2.f, s, -1.f), 1.f - s); // l?s:1-s
            lg   += __log2f(sel);
            pcnt += l;
            psum  = fmaf(l, s, psum);
        }
    } else if (e0 < len) {                // the single boundary thread
#pragma unroll
        for (int k = 0; k < 4; ++k) {
            if (e0 + k < len) {
                const float s = sv[k], l = lv[k];
                const float sel = fmaf(l, fmaf(2.f, s, -1.f), 1.f - s);
                lg   += __log2f(sel);
                pcnt += l;
                psum  = fmaf(l, s, psum);
            }
        }
    }
    // -100 clamp of reference is inert: scores in (1e-4,1-1e-4) => |log| <= 9.3
    float bce = -0.693147180559945f * lg;

#pragma unroll
    for (int o = 16; o; o >>= 1) {
        bce  += __shfl_down_sync(FULL, bce,  o);
        pcnt += __shfl_down_sync(FULL, pcnt, o);
        psum += __shfl_down_sync(FULL, psum, o);
    }
    __shared__ float shA[8], shB[8], shC[8], shH[8];
    const int w = tid >> 5, lane = tid & 31;
    if (lane == 0) { shA[w] = bce; shB[w] = pcnt; shC[w] = psum; }
    __syncthreads();

    // all threads form block totals (saves a barrier)
    float bce_t = 0.f, pc_t = 0.f, ps_t = 0.f;
#pragma unroll
    for (int i = 0; i < 8; ++i) { bce_t += shA[i]; pc_t += shB[i]; ps_t += shC[i]; }
    const float chosen = (pc_t > 0.f) ? ps_t : -MARGIN;
    const float cm = MARGIN - chosen;

    // ---- pass 2: hinge over valid negatives (registers only) ----
    float hinge = 0.f;
    if (e0 + 4 <= len) {
#pragma unroll
        for (int k = 0; k < 4; ++k) {
            const float h = fmaxf(sv[k] + cm, 0.f);
            hinge = fmaf(1.f - lv[k], h, hinge);      // labels exactly {0,1}
        }
    } else if (e0 < len) {
#pragma unroll
        for (int k = 0; k < 4; ++k) {
            if (e0 + k < len && lv[k] != 1.0f)
                hinge += fmaxf(sv[k] + cm, 0.f);
        }
    }
#pragma unroll
    for (int o = 16; o; o >>= 1)
        hinge += __shfl_down_sync(FULL, hinge, o);
    if (lane == 0) shH[w] = hinge;
    __syncthreads();

    if (tid == 0) {
        float hsum = 0.f;
#pragma unroll
        for (int i = 0; i < 8; ++i) hsum += shH[i];
        const float flen = (float)len;
        const float negc = flen - pc_t;
        const bool  val  = (len > 0) && (negc > 0.f);
        g_row_bce[row]   = bce_t / ((float)Ln * flen); // (bce*mask).mean(1)/mask.sum(1)
        g_row_hinge[row] = val ? hsum / fmaxf(negc, 1.0f) : 0.f;
        g_row_valid[row] = val ? 1.0f : 0.f;
    }
}

// 16-block final reduce: one row per thread, deterministic Q32.32 combine.
__global__ void __launch_bounds__(512)
final_kernel(const float* __restrict__ sim, float* __restrict__ out)
{
    const int tid = threadIdx.x;
    const int r   = blockIdx.x * 512 + tid;
    const unsigned FULL = 0xffffffffu;

    float b = g_row_bce[r];
    float h = g_row_hinge[r];
    float v = g_row_valid[r];
    float s = sim[r];

#pragma unroll
    for (int o = 16; o; o >>= 1) {
        b += __shfl_down_sync(FULL, b, o);
        h += __shfl_down_sync(FULL, h, o);
        v += __shfl_down_sync(FULL, v, o);
        s += __shfl_down_sync(FULL, s, o);
    }
    __shared__ float sb[16], sh[16], sv_[16], ss[16];
    const int w = tid >> 5, lane = tid & 31;
    if (lane == 0) { sb[w] = b; sh[w] = h; sv_[w] = v; ss[w] = s; }
    __syncthreads();

    if (tid == 0) {
        float B2 = 0.f, H = 0.f, V = 0.f, S = 0.f;
#pragma unroll
        for (int i = 0; i < 16; ++i) { B2 += sb[i]; H += sh[i]; V += sv_[i]; S += ss[i]; }

        const double SC = 4294967296.0;
        atomicAdd(&g_acc_bce,   (unsigned long long)__double2ll_rn((double)B2 * SC));
        atomicAdd(&g_acc_hinge, (unsigned long long)__double2ll_rn((double)H  * SC));
        atomicAdd(&g_acc_valid, (unsigned long long)(long long)(V + 0.5f));
        atomicAdd(&g_acc_sim,   (unsigned long long)__double2ll_rn((double)S  * SC));

        __threadfence();
        const unsigned ticket = atomicAdd(&g_done, 1u);
        if (ticket == (unsigned)(FBLK - 1)) {
            const long long ib = (long long)atomicExch(&g_acc_bce,   0ULL);
            const long long ih = (long long)atomicExch(&g_acc_hinge, 0ULL);
            const long long iv = (long long)atomicExch(&g_acc_valid, 0ULL);
            const long long is = (long long)atomicExch(&g_acc_sim,   0ULL);
            atomicExch(&g_done, 0u);

            const double INV = 1.0 / 4294967296.0;
            const double Bsum = (double)ib * INV;
            const double Hsum = (double)ih * INV;
            const double Vcnt = (double)iv;
            const double Ssum = (double)is * INV;

            const double bce_loss   = Bsum / (double)Bn;
            const double hinge_loss = (Vcnt > 0.0) ? Hsum / ((Vcnt > 1.0) ? Vcnt : 1.0) : 0.0;
            const double sim_loss   = -Ssum / (double)Bn;
            const double combined   = hinge_loss + bce_loss + sim_loss;
            out[0] = (float)combined;
            out[1] = (float)hinge_loss;
            out[2] = (float)bce_loss;
            out[3] = (float)sim_loss;
        }
    }
}

extern "C" void kernel_launch(void* const* d_in, const int* in_sizes, int n_in,
                              void* d_out, int out_size)
{
    const float4* scores4 = (const float4*)d_in[0];
    const int*    lens    = (const int*)d_in[1];
    const float4* labels4 = (const float4*)d_in[2];
    const float*  sim     = (const float*)d_in[3];
    float* out = (float*)d_out;

    row_kernel<<<Bn, 256>>>(scores4, lens, labels4);
    final_kernel<<<FBLK, 512>>>(sim, out);
}

// round 13
// speedup vs baseline: 1.5517x; 1.4871x over previous
#include <cuda_runtime.h>

#define MARGIN 0.1f
constexpr int Bn = 8192;
constexpr int Ln = 1024;
constexpr int WPB = 8;                 // one row per warp
constexpr int BLOCKS = Bn / WPB;       // 1024

// Deterministic Q32.32 fixed-point accumulators (integer atomics = associative).
// Last block drains via atomicExch -> zeroed for the next graph replay.
__device__ unsigned long long g_acc_bce, g_acc_hinge, g_acc_valid, g_acc_sim;
__device__ unsigned int       g_done;

__global__ void __launch_bounds__(256)
fused_kernel(const float4* __restrict__ scores4,
             const int*    __restrict__ lens,
             const float4* __restrict__ labels4,
             const float*  __restrict__ sim,
             float*        __restrict__ out)
{
    // Per-warp stash of this row's scores: pass 2 runs from SMEM (29cyc LDS)
    // instead of re-walking L2 (234+cyc). 8 warps * 256 float4 = 32KB.
    __shared__ float4 s_sc[WPB][Ln / 4];

    const int tid  = threadIdx.x;
    const int wid  = tid >> 5;
    const int lane = tid & 31;
    const unsigned FULL = 0xffffffffu;

    const int row = blockIdx.x * WPB + wid;
    const int len = lens[row];
    const int ngf = len >> 7;                    // fully-valid 128-elem groups
    const int ng  = (len + 127) >> 7;            // total valid groups (>=1)
    const float4* __restrict__ srow = scores4 + row * (Ln / 4);
    const float4* __restrict__ lrow = labels4 + row * (Ln / 4);
    const float simv = (lane == 0) ? sim[row] : 0.f;   // early; hidden by pass 1

    // ---- pass 1: BCE(log2), pos count/score, pos bitmask; 2 groups/iter (MLP 4) ----
    float lg = 0.f, pcnt = 0.f, psum = 0.f;
    unsigned pmask = 0u;                          // bit (4j+k): valid positive

    int j = 0;
    for (; j + 2 <= ngf; j += 2) {
        // 4 independent LDG.128 in flight before any consumption
        const float4 sa = srow[lane + 32 * j];
        const float4 la = lrow[lane + 32 * j];
        const float4 sb = srow[lane + 32 * (j + 1)];
        const float4 lb = lrow[lane + 32 * (j + 1)];
        {
            const float sv[4] = {sa.x, sa.y, sa.z, sa.w};
            const float lv[4] = {la.x, la.y, la.z, la.w};
#pragma unroll
            for (int k = 0; k < 4; ++k) {
                const float s = sv[k], l = lv[k];
                const float sel = fmaf(l, fmaf(2.f, s, -1.f), 1.f - s); // l?s:1-s
                lg   += __log2f(sel);
                pcnt += l;
                psum  = fmaf(l, s, psum);
                pmask |= (unsigned)(l == 1.0f) << (4 * j + k);
            }
        }
        {
            const float sv[4] = {sb.x, sb.y, sb.z, sb.w};
            const float lv[4] = {lb.x, lb.y, lb.z, lb.w};
#pragma unroll
            for (int k = 0; k < 4; ++k) {
                const float s = sv[k], l = lv[k];
                const float sel = fmaf(l, fmaf(2.f, s, -1.f), 1.f - s);
                lg   += __log2f(sel);
                pcnt += l;
                psum  = fmaf(l, s, psum);
                pmask |= (unsigned)(l == 1.0f) << (4 * (j + 1) + k);
            }
        }
        s_sc[wid][lane + 32 * j]       = sa;      // STS.128, issue-only
        s_sc[wid][lane + 32 * (j + 1)] = sb;
    }
    if (j < ngf) {                                // leftover single full group
        const float4 sa = srow[lane + 32 * j];
        const float4 la = lrow[lane + 32 * j];
        const float sv[4] = {sa.x, sa.y, sa.z, sa.w};
        const float lv[4] = {la.x, la.y, la.z, la.w};
#pragma unroll
        for (int k = 0; k < 4; ++k) {
            const float s = sv[k], l = lv[k];
            const float sel = fmaf(l, fmaf(2.f, s, -1.f), 1.f - s);
            lg   += __log2f(sel);
            pcnt += l;
            psum  = fmaf(l, s, psum);
            pmask |= (unsigned)(l == 1.0f) << (4 * j + k);
        }
        s_sc[wid][lane + 32 * j] = sa;
        ++j;
    }
    if (j < ng) {                                 // boundary group (len & 127)
        const float4 sa = srow[lane + 32 * j];
        const float4 la = lrow[lane + 32 * j];
        const float sv[4] = {sa.x, sa.y, sa.z, sa.w};
        const float lv[4] = {la.x, la.y, la.z, la.w};
        const int e0 = 4 * (lane + 32 * j);
#pragma unroll
        for (int k = 0; k < 4; ++k) {
            if (e0 + k < len) {
                const float s = sv[k], l = lv[k];
                const float sel = fmaf(l, fmaf(2.f, s, -1.f), 1.f - s);
                lg   += __log2f(sel);
                pcnt += l;
                psum  = fmaf(l, s, psum);
                pmask |= (unsigned)(l == 1.0f) << (4 * j + k);
            }
        }
        s_sc[wid][lane + 32 * j] = sa;
    }
    // -100 clamp of reference is inert: scores in (1e-4,1-1e-4) => |log| <= 9.3
    const float bce = -0.693147180559945f * lg;

    // butterfly so every lane holds chosen (bit-deterministic)
    float pc_t = pcnt, ps_t = psum;
#pragma unroll
    for (int o = 16; o; o >>= 1) {
        pc_t += __shfl_xor_sync(FULL, pc_t, o);
        ps_t += __shfl_xor_sync(FULL, ps_t, o);
    }
    const float chosen = (pc_t > 0.f) ? ps_t : -MARGIN;
    const float cm = MARGIN - chosen;

    // ---- pass 2: hinge over valid negatives, entirely from SMEM ----
    // (each lane reads back its own stashed float4s: no sync needed)
    float hinge = 0.f;
    for (int g = 0; g < ngf; ++g) {
        const float4 s4 = s_sc[wid][lane + 32 * g];
        const float sv[4] = {s4.x, s4.y, s4.z, s4.w};
#pragma unroll
        for (int k = 0; k < 4; ++k) {
            const float h = fmaxf(sv[k] + cm, 0.f);
            hinge += ((pmask >> (4 * g + k)) & 1u) ? 0.f : h;
        }
    }
    if (ngf < ng) {
        const int g = ngf;
        const float4 s4 = s_sc[wid][lane + 32 * g];
        const float sv[4] = {s4.x, s4.y, s4.z, s4.w};
        const int e0 = 4 * (lane + 32 * g);
#pragma unroll
        for (int k = 0; k < 4; ++k) {
            if (e0 + k < len && !((pmask >> (4 * g + k)) & 1u))
                hinge += fmaxf(sv[k] + cm, 0.f);
        }
    }

    // fused reduce of (bce, hinge) to lane 0
    float bce_r = bce, h_r = hinge;
#pragma unroll
    for (int o = 16; o; o >>= 1) {
        bce_r += __shfl_down_sync(FULL, bce_r, o);
        h_r   += __shfl_down_sync(FULL, h_r,   o);
    }

    // ---- per-warp row result -> shared; one barrier; one atomic set/block ----
    __shared__ float fin[WPB][4];
    if (lane == 0) {
        const float flen = (float)len;
        const float negc = flen - pc_t;
        const bool  val  = (len > 0) && (negc > 0.f);
        fin[wid][0] = bce_r / ((float)Ln * flen);  // (bce*mask).mean(1)/mask.sum(1)
        fin[wid][1] = val ? h_r / fmaxf(negc, 1.0f) : 0.f;
        fin[wid][2] = val ? 1.0f : 0.f;
        fin[wid][3] = simv;
    }
    __syncthreads();

    if (tid == 0) {
        float bb = 0.f, hb = 0.f, vb = 0.f, sb = 0.f;
#pragma unroll
        for (int i = 0; i < WPB; ++i) {
            bb += fin[i][0]; hb += fin[i][1]; vb += fin[i][2]; sb += fin[i][3];
        }
        const double SC = 4294967296.0;
        atomicAdd(&g_acc_bce,   (unsigned long long)__double2ll_rn((double)bb * SC));
        atomicAdd(&g_acc_hinge, (unsigned long long)__double2ll_rn((double)hb * SC));
        atomicAdd(&g_acc_valid, (unsigned long long)(long long)(vb + 0.5f));
        atomicAdd(&g_acc_sim,   (unsigned long long)__double2ll_rn((double)sb * SC));

        __threadfence();
        const unsigned ticket = atomicAdd(&g_done, 1u);
        if (ticket == (unsigned)(BLOCKS - 1)) {
            const long long ib = (long long)atomicExch(&g_acc_bce,   0ULL);
            const long long ih = (long long)atomicExch(&g_acc_hinge, 0ULL);
            const long long iv = (long long)atomicExch(&g_acc_valid, 0ULL);
            const long long is = (long long)atomicExch(&g_acc_sim,   0ULL);
            atomicExch(&g_done, 0u);

            const double INV = 1.0 / 4294967296.0;
            const double Bsum = (double)ib * INV;
            const double Hsum = (double)ih * INV;
            const double Vcnt = (double)iv;
            const double Ssum = (double)is * INV;

            const double bce_loss   = Bsum / (double)Bn;
            const double hinge_loss = (Vcnt > 0.0) ? Hsum / ((Vcnt > 1.0) ? Vcnt : 1.0) : 0.0;
            const double sim_loss   = -Ssum / (double)Bn;
            const double combined   = hinge_loss + bce_loss + sim_loss;
            out[0] = (float)combined;
            out[1] = (float)hinge_loss;
            out[2] = (float)bce_loss;
            out[3] = (float)sim_loss;
        }
    }
}

extern "C" void kernel_launch(void* const* d_in, const int* in_sizes, int n_in,
                              void* d_out, int out_size)
{
    const float4* scores4 = (const float4*)d_in[0];
    const int*    lens    = (const int*)d_in[1];
    const float4* labels4 = (const float4*)d_in[2];
    const float*  sim     = (const float*)d_in[3];
    float* out = (float*)d_out;

    fused_kernel<<<BLOCKS, WPB * 32>>>(scores4, lens, labels4, sim, out);
}